// round 16
// baseline (speedup 1.0000x reference)
#include <cuda_runtime.h>
#include <cuda_bf16.h>

#define N_NODE   100000
#define N_REL    8
#define EMB      32
#define OUT      32
#define NE       1600000
#define BATCH    16384
#define H1       64
#define H2       32
#define H3       16
#define CAP      128    // global bucket capacity
#define CAPS     96     // cached/processed cap (P(deg>96) ~ 1e-45, Poisson(16))
#define DSJB     296    // dsj blocks inside prep_k

typedef unsigned long long ull;

// ---------------- scratch (static device globals; no allocation) ----------------
__device__ float  g_w[N_REL * EMB * OUT];        // relation weights w[r][f][o]
__device__ float2 g_dsj[N_NODE * N_REL];         // {di, sj} per (node,rel)
__device__ float  g_h[N_NODE * OUT];             // final node features (needed rows only)
__device__ int    g_need[N_NODE];
__device__ int    g_cntr[N_NODE];                // bucket cursor / degree
__device__ int    g_nlist[N_NODE];               // compact list of needed nodes
__device__ int    g_ebuf[(size_t)N_NODE * CAP];  // fixed-stride buckets: src*8+t
__device__ int    g_ncnt;

// packed f32x2 ops (Blackwell)
__device__ __forceinline__ ull fma2(ull a, ull b, ull c) {
    ull d;
    asm("fma.rn.f32x2 %0, %1, %2, %3;" : "=l"(d) : "l"(a), "l"(b), "l"(c));
    return d;
}
__device__ __forceinline__ float fold2(ull a) {
    float lo, hi;
    asm("mov.b64 {%0,%1}, %2;" : "=f"(lo), "=f"(hi) : "l"(a));
    return lo + hi;
}
__device__ __forceinline__ ull pack2(float lo, float hi) {
    ull d;
    asm("mov.b64 %0, {%1,%2};" : "=l"(d) : "f"(lo), "f"(hi));
    return d;
}
__device__ __forceinline__ float2 unpk2(ull a) {
    float lo, hi;
    asm("mov.b64 {%0,%1}, %2;" : "=f"(lo), "=f"(hi) : "l"(a));
    return make_float2(lo, hi);
}

// ---------------- K0: fused basis GEMM (blocks 0..31) + scratch zeroing ----------------
__global__ void initbasis_k(const float* __restrict__ weight, const float* __restrict__ basis) {
    int b = blockIdx.x;
    int tid = threadIdx.x;
    if (b < 32) {
        int gid = b * 256 + tid;
        int r = gid >> 10, fo = gid & 1023;
        float acc = 0.f;
        #pragma unroll
        for (int k = 0; k < 30; k++)
            acc += __ldg(weight + r * 30 + k) * __ldg(basis + k * 1024 + fo);
        g_w[r * 1024 + fo] = acc;
        if (gid == 0) g_ncnt = 0;
    } else {
        int i = (b - 32) * 256 + tid;
        int stride = (gridDim.x - 32) * 256;
        for (int j = i; j < N_NODE; j += stride) { g_need[j] = 0; g_cntr[j] = 0; }
    }
}

// ---------------- K1: mark needed dst nodes + compact list ----------------
__global__ void mark_k(const int* __restrict__ users, const int* __restrict__ bundles) {
    int i = blockIdx.x * blockDim.x + threadIdx.x;
    if (i >= 2 * BATCH) return;
    int u = (i < BATCH) ? users[i] : bundles[i - BATCH];
    if (atomicExch(&g_need[u], 1) == 0) {
        int p = atomicAdd(&g_ncnt, 1);
        g_nlist[p] = u;
    }
}

// ---------------- K2: fused {bucket fill} + {di,sj} (independent work, one launch) ----------------
// blocks [0, DSJB): dsj — 4 thread-slots per node, 2 relations each, x row in registers.
// blocks [DSJB, grid): grid-stride bucket fill of active edges.
__global__ void prep_k(const int* __restrict__ x_ids, const float* __restrict__ emb,
                       const float* __restrict__ att,
                       const int* __restrict__ ei, const int* __restrict__ et) {
    int tid = threadIdx.x;
    if (blockIdx.x < DSJB) {
        __shared__ float swa1[N_REL * EMB];
        __shared__ float swa2[N_REL * EMB];
        {   // wa prologue: thread=(r,f)
            int r = tid >> 5, f = tid & 31;
            const float4* wr = (const float4*)(g_w + (r * EMB + f) * OUT);
            const float* a1 = att + r * 64;
            const float* a2 = a1 + 32;
            float s1 = 0.f, s2 = 0.f;
            #pragma unroll
            for (int q = 0; q < 8; q++) {
                float4 wv = __ldg(wr + q);
                s1 += wv.x * __ldg(a1 + 4 * q)     + wv.y * __ldg(a1 + 4 * q + 1)
                    + wv.z * __ldg(a1 + 4 * q + 2) + wv.w * __ldg(a1 + 4 * q + 3);
                s2 += wv.x * __ldg(a2 + 4 * q)     + wv.y * __ldg(a2 + 4 * q + 1)
                    + wv.z * __ldg(a2 + 4 * q + 2) + wv.w * __ldg(a2 + 4 * q + 3);
            }
            swa1[r * EMB + f] = s1;
            swa2[r * EMB + f] = s2;
        }
        __syncthreads();

        int slot = blockIdx.x * 256 + tid;
        int nslots = DSJB * 256;
        for (int idx = slot; idx < 4 * N_NODE; idx += nslots) {
            int n = idx >> 2;
            int rbase = (idx & 3) * 2;
            const float4* xr = (const float4*)(emb + (size_t)__ldg(x_ids + n) * EMB);
            ull xv[16];
            #pragma unroll
            for (int q = 0; q < 8; q++) {
                float4 v = __ldg(xr + q);
                xv[2 * q]     = pack2(v.x, v.y);
                xv[2 * q + 1] = pack2(v.z, v.w);
            }
            #pragma unroll
            for (int k = 0; k < 2; k++) {
                int rr = rbase + k;
                const ull* w1p = (const ull*)(swa1 + rr * EMB);
                const ull* w2p = (const ull*)(swa2 + rr * EMB);
                ull aD = 0ULL, aS = 0ULL;
                #pragma unroll
                for (int q = 0; q < 16; q++) {
                    aD = fma2(xv[q], w1p[q], aD);
                    aS = fma2(xv[q], w2p[q], aS);
                }
                g_dsj[(size_t)n * N_REL + rr] = make_float2(fold2(aD), fold2(aS));
            }
        }
    } else {
        int base = (blockIdx.x - DSJB) * 256 + tid;
        int stride = (gridDim.x - DSJB) * 256;
        for (int e = base; e < NE; e += stride) {
            int dst = ei[NE + e];
            if (!g_need[dst]) continue;
            int pos = atomicAdd(&g_cntr[dst], 1);
            if (pos < CAP)
                g_ebuf[(size_t)dst * CAP + pos] = ei[e] * N_REL + et[e];
        }
    }
}

// ---------------- K3: persistent per-node aggregation + packed transform ----------------
__global__ void nodeagg_k(const int* __restrict__ x_ids, const float* __restrict__ emb,
                          const float* __restrict__ root, const float* __restrict__ bias) {
    __shared__ ull   swt2[N_REL * 16 * OUT];   // 32 KB  {w[t][2q][o], w[t][2q+1][o]}
    __shared__ ull   sroot2[16 * OUT];         // 4 KB
    __shared__ int   sst[4][CAPS];             // cached xsrc*8+t
    __shared__ float swx[4][CAPS];             // cached ex
    __shared__ float sv[4][288];               // staged v (256) + x row (32)

    int tid = threadIdx.x;   // 128
    int wid = tid >> 5, lane = tid & 31;

    for (int i = tid; i < N_REL * 16 * OUT; i += 128) {
        int o = i & 31, q = (i >> 5) & 15, t = i >> 9;
        swt2[i] = pack2(g_w[t * 1024 + (2 * q) * 32 + o], g_w[t * 1024 + (2 * q + 1) * 32 + o]);
    }
    for (int i = tid; i < 16 * OUT; i += 128) {
        int o = i & 31, q = i >> 5;
        sroot2[i] = pack2(__ldg(root + (2 * q) * 32 + o), __ldg(root + (2 * q + 1) * 32 + o));
    }
    __syncthreads();

    float bia = __ldg(bias + lane);
    int ncnt = g_ncnt;
    int step = gridDim.x * 4;

    for (int widx = blockIdx.x * 4 + wid; widx < ncnt; widx += step) {
        int n   = g_nlist[widx];
        int deg = g_cntr[n];
        if (deg > CAPS) deg = CAPS;
        const int* ebase = g_ebuf + (size_t)n * CAP;

        float dv = (lane < N_REL) ? g_dsj[n * N_REL + lane].x : 0.f;

        // ---- phase 1: lane-parallel ex + denominators + x_ids translation ----
        float pden[N_REL];
        #pragma unroll
        for (int t8 = 0; t8 < N_REL; t8++) pden[t8] = 0.f;

        for (int c = 0; c < deg; c += 32) {
            int j = c + lane;
            bool v = (j < deg);
            int st = 0;
            float ex = 0.f;
            int t = 0;
            if (v) {
                st = __ldg(&ebase[j]);
                t = st & 7;
            }
            float di = __shfl_sync(0xffffffffu, dv, t);
            if (v) {
                float sj = __ldg(&((const float*)g_dsj)[2 * st + 1]);
                float s = di + sj;
                s = (s > 0.f) ? s : 0.2f * s;
                ex = __expf(s);
                int xsrc = __ldg(x_ids + (st >> 3));
                sst[wid][j] = (xsrc << 3) | t;
                swx[wid][j] = ex;
            }
            #pragma unroll
            for (int t8 = 0; t8 < N_REL; t8++)
                pden[t8] += (v && t == t8) ? ex : 0.f;
        }

        float rden[N_REL];
        #pragma unroll
        for (int t8 = 0; t8 < N_REL; t8++) {
            float s = pden[t8];
            #pragma unroll
            for (int o = 16; o > 0; o >>= 1) s += __shfl_xor_sync(0xffffffffu, s, o);
            rden[t8] = 1.f / (s + 1e-16f);
        }
        __syncwarp();

        // ---- phase 2: accumulate v_t in embedding space (lane = f) ----
        float v[N_REL];
        #pragma unroll
        for (int t8 = 0; t8 < N_REL; t8++) v[t8] = 0.f;

        #pragma unroll 4
        for (int j = 0; j < deg; j++) {
            int stj  = sst[wid][j];
            float exj = swx[wid][j];
            float xv = __ldg(emb + (size_t)(stj >> 3) * EMB + lane);
            float m = xv * exj;
            int t = stj & 7;
            #pragma unroll
            for (int t8 = 0; t8 < N_REL; t8++)
                v[t8] += (t == t8) ? m : 0.f;
        }

        // stage normalized v + x row into warp-private smem
        #pragma unroll
        for (int t8 = 0; t8 < N_REL; t8++)
            sv[wid][t8 * 32 + lane] = v[t8] * rden[t8];
        int xn = __ldg(x_ids + n);
        sv[wid][256 + lane] = __ldg(emb + (size_t)xn * EMB + lane);
        __syncwarp();

        // ---- packed transform: acc[o] = bias + sum v@w + x@root (lane = o) ----
        const ull* svp = (const ull*)sv[wid];
        ull accA = 0ULL, accB = 0ULL;
        #pragma unroll 16
        for (int u = 0; u < 128; u += 2) {
            accA = fma2(svp[u],     swt2[u * 32 + lane],       accA);
            accB = fma2(svp[u + 1], swt2[(u + 1) * 32 + lane], accB);
        }
        #pragma unroll
        for (int q = 0; q < 16; q += 2) {
            accA = fma2(svp[128 + q],     sroot2[q * 32 + lane],       accA);
            accB = fma2(svp[128 + q + 1], sroot2[(q + 1) * 32 + lane], accB);
        }
        float acc = fold2(accA) + fold2(accB) + bia;
        g_h[n * OUT + lane] = fmaxf(acc, 0.f);
        __syncwarp();   // protect sst/swx/sv before next node reuses them
    }
}

// ---------------- K4: MLP, fully FFMA2-packed ----------------
__global__ void mlp_k(const int* __restrict__ users, const int* __restrict__ bundles,
                      const float* __restrict__ W1, const float* __restrict__ b1,
                      const float* __restrict__ W2, const float* __restrict__ b2,
                      const float* __restrict__ W3, const float* __restrict__ b3,
                      const float* __restrict__ Wo, const float* __restrict__ bo,
                      float* __restrict__ out) {
    __shared__ ull   sW1p[32 * H1];     // 16 KB {W1[2k][j], W1[2k+1][j]}
    __shared__ ull   sW2u[H1 * H2 / 2]; // 8 KB  natural row pairs
    __shared__ ull   sW3u[H2 * H3 / 2]; // 2 KB
    __shared__ float sWo[H3];
    __shared__ float sb1[H1], sb2[H2], sb3[H3];

    int tid = threadIdx.x;   // 64
    for (int i = tid; i < 32 * H1; i += 64) {
        int k2 = i >> 6, j = i & 63;
        sW1p[i] = pack2(__ldg(W1 + (2 * k2) * H1 + j), __ldg(W1 + (2 * k2 + 1) * H1 + j));
    }
    {
        const float2* W2v = (const float2*)W2;
        for (int i = tid; i < H1 * H2 / 2; i += 64) {
            float2 v = __ldg(W2v + i);
            sW2u[i] = pack2(v.x, v.y);
        }
        const float2* W3v = (const float2*)W3;
        for (int i = tid; i < H2 * H3 / 2; i += 64) {
            float2 v = __ldg(W3v + i);
            sW3u[i] = pack2(v.x, v.y);
        }
    }
    if (tid < H3) sWo[tid] = Wo[tid];
    if (tid < H1) sb1[tid] = b1[tid];
    if (tid < H2) sb2[tid] = b2[tid];
    if (tid < H3) sb3[tid] = b3[tid];
    __syncthreads();

    int b = blockIdx.x * 64 + tid;
    if (b >= BATCH) return;

    int nu = users[b], nb = bundles[b];
    ull z2[32];
    const float4* hu = (const float4*)(g_h + (size_t)nu * OUT);
    const float4* hb = (const float4*)(g_h + (size_t)nb * OUT);
    #pragma unroll
    for (int k = 0; k < 8; k++) {
        float4 v = __ldg(hu + k);
        z2[2 * k]     = pack2(v.x, v.y);
        z2[2 * k + 1] = pack2(v.z, v.w);
    }
    #pragma unroll
    for (int k = 0; k < 8; k++) {
        float4 v = __ldg(hb + k);
        z2[16 + 2 * k]     = pack2(v.x, v.y);
        z2[16 + 2 * k + 1] = pack2(v.z, v.w);
    }

    // stage 1 + 2 streamed, packed
    ull a2p[16];
    #pragma unroll
    for (int m = 0; m < 16; m++) a2p[m] = pack2(sb2[2 * m], sb2[2 * m + 1]);
    for (int j = 0; j < H1; j++) {
        ull tA = 0ULL, tB = 0ULL;
        #pragma unroll
        for (int k2 = 0; k2 < 32; k2 += 2) {
            tA = fma2(z2[k2],     sW1p[k2 * 64 + j],       tA);
            tB = fma2(z2[k2 + 1], sW1p[(k2 + 1) * 64 + j], tB);
        }
        float t = fold2(tA) + fold2(tB) + sb1[j];
        t = fmaxf(t, 0.f);
        ull tt = pack2(t, t);
        #pragma unroll
        for (int m = 0; m < 16; m++)
            a2p[m] = fma2(tt, sW2u[j * 16 + m], a2p[m]);
    }
    float a2v[H2];
    #pragma unroll
    for (int m = 0; m < 16; m++) {
        float2 p = unpk2(a2p[m]);
        a2v[2 * m]     = fmaxf(p.x, 0.f);
        a2v[2 * m + 1] = fmaxf(p.y, 0.f);
    }

    // stage 3 packed
    ull a3p[8];
    #pragma unroll
    for (int m = 0; m < 8; m++) a3p[m] = pack2(sb3[2 * m], sb3[2 * m + 1]);
    #pragma unroll
    for (int j = 0; j < H2; j++) {
        ull tt = pack2(a2v[j], a2v[j]);
        #pragma unroll
        for (int m = 0; m < 8; m++)
            a3p[m] = fma2(tt, sW3u[j * 8 + m], a3p[m]);
    }
    float o = __ldg(bo);
    #pragma unroll
    for (int m = 0; m < 8; m++) {
        float2 p = unpk2(a3p[m]);
        o += fmaxf(p.x, 0.f) * sWo[2 * m] + fmaxf(p.y, 0.f) * sWo[2 * m + 1];
    }
    out[b] = o;
}

// ---------------- launch ----------------
extern "C" void kernel_launch(void* const* d_in, const int* in_sizes, int n_in,
                              void* d_out, int out_size) {
    const int*   x_ids      = (const int*)d_in[0];
    const int*   edge_index = (const int*)d_in[1];
    const int*   edge_type  = (const int*)d_in[2];
    const int*   users      = (const int*)d_in[3];
    const int*   bundles    = (const int*)d_in[4];
    const float* emb        = (const float*)d_in[5];
    const float* basis      = (const float*)d_in[6];
    const float* weight     = (const float*)d_in[7];
    const float* att        = (const float*)d_in[8];
    const float* root       = (const float*)d_in[9];
    const float* bias       = (const float*)d_in[10];
    const float* W1         = (const float*)d_in[11];
    const float* b1         = (const float*)d_in[12];
    const float* W2         = (const float*)d_in[13];
    const float* b2         = (const float*)d_in[14];
    const float* W3         = (const float*)d_in[15];
    const float* b3         = (const float*)d_in[16];
    const float* Wo         = (const float*)d_in[17];
    const float* bo         = (const float*)d_in[18];
    float* out = (float*)d_out;

    initbasis_k<<<32 + 256, 256>>>(weight, basis);                    // 0
    mark_k<<<(2 * BATCH + 255) / 256, 256>>>(users, bundles);         // 1
    prep_k<<<DSJB + 1184, 256>>>(x_ids, emb, att,
                                 edge_index, edge_type);              // 2
    nodeagg_k<<<592, 128>>>(x_ids, emb, root, bias);                  // 3  <- profiled
    mlp_k<<<BATCH / 64, 64>>>(users, bundles,
                              W1, b1, W2, b2, W3, b3, Wo, bo, out);   // 4
}

// round 17
// speedup vs baseline: 1.0386x; 1.0386x over previous
#include <cuda_runtime.h>
#include <cuda_bf16.h>

#define N_NODE   100000
#define N_REL    8
#define EMB      32
#define OUT      32
#define NE       1600000
#define BATCH    16384
#define H1       64
#define H2       32
#define H3       16
#define SUBCAP   16     // per-(dst,rel) bucket capacity (Poisson(2); P(drop)~1e-11)
#define DSJB     296    // dsj blocks inside prep_k

typedef unsigned long long ull;

// ---------------- scratch (static device globals; no allocation) ----------------
__device__ float  g_w[N_REL * EMB * OUT];        // relation weights w[r][f][o]
__device__ float2 g_dsj[N_NODE * N_REL];         // {di, sj} per (node,rel)
__device__ float  g_h[N_NODE * OUT];             // final node features (needed rows only)
__device__ int    g_need[N_NODE];
__device__ int    g_cntr8[N_NODE * N_REL];       // per-(dst,rel) bucket cursor
__device__ int    g_nlist[N_NODE];               // compact list of needed nodes
__device__ int    g_ebuf[(size_t)N_NODE * 128];  // rel-sorted buckets: [dst][t*16+j] = src
__device__ int    g_ncnt;

// packed f32x2 ops (Blackwell)
__device__ __forceinline__ ull fma2(ull a, ull b, ull c) {
    ull d;
    asm("fma.rn.f32x2 %0, %1, %2, %3;" : "=l"(d) : "l"(a), "l"(b), "l"(c));
    return d;
}
__device__ __forceinline__ float fold2(ull a) {
    float lo, hi;
    asm("mov.b64 {%0,%1}, %2;" : "=f"(lo), "=f"(hi) : "l"(a));
    return lo + hi;
}
__device__ __forceinline__ ull pack2(float lo, float hi) {
    ull d;
    asm("mov.b64 %0, {%1,%2};" : "=l"(d) : "f"(lo), "f"(hi));
    return d;
}
__device__ __forceinline__ float2 unpk2(ull a) {
    float lo, hi;
    asm("mov.b64 {%0,%1}, %2;" : "=f"(lo), "=f"(hi) : "l"(a));
    return make_float2(lo, hi);
}

// ---------------- K0: fused basis GEMM (blocks 0..31) + scratch zeroing ----------------
__global__ void initbasis_k(const float* __restrict__ weight, const float* __restrict__ basis) {
    int b = blockIdx.x;
    int tid = threadIdx.x;
    if (b < 32) {
        int gid = b * 256 + tid;
        int r = gid >> 10, fo = gid & 1023;
        float acc = 0.f;
        #pragma unroll
        for (int k = 0; k < 30; k++)
            acc += __ldg(weight + r * 30 + k) * __ldg(basis + k * 1024 + fo);
        g_w[r * 1024 + fo] = acc;
        if (gid == 0) g_ncnt = 0;
    } else {
        int i = (b - 32) * 256 + tid;
        int stride = (gridDim.x - 32) * 256;
        for (int j = i; j < N_NODE * N_REL; j += stride) g_cntr8[j] = 0;
        for (int j = i; j < N_NODE; j += stride) g_need[j] = 0;
    }
}

// ---------------- K1: mark needed dst nodes + compact list ----------------
__global__ void mark_k(const int* __restrict__ users, const int* __restrict__ bundles) {
    int i = blockIdx.x * blockDim.x + threadIdx.x;
    if (i >= 2 * BATCH) return;
    int u = (i < BATCH) ? users[i] : bundles[i - BATCH];
    if (atomicExch(&g_need[u], 1) == 0) {
        int p = atomicAdd(&g_ncnt, 1);
        g_nlist[p] = u;
    }
}

// ---------------- K2: fused {rel-sorted bucket fill} + {di,sj} ----------------
__global__ void prep_k(const int* __restrict__ x_ids, const float* __restrict__ emb,
                       const float* __restrict__ att,
                       const int* __restrict__ ei, const int* __restrict__ et) {
    int tid = threadIdx.x;
    if (blockIdx.x < DSJB) {
        __shared__ float swa1[N_REL * EMB];
        __shared__ float swa2[N_REL * EMB];
        {   // wa prologue: thread=(r,f)
            int r = tid >> 5, f = tid & 31;
            const float4* wr = (const float4*)(g_w + (r * EMB + f) * OUT);
            const float* a1 = att + r * 64;
            const float* a2 = a1 + 32;
            float s1 = 0.f, s2 = 0.f;
            #pragma unroll
            for (int q = 0; q < 8; q++) {
                float4 wv = __ldg(wr + q);
                s1 += wv.x * __ldg(a1 + 4 * q)     + wv.y * __ldg(a1 + 4 * q + 1)
                    + wv.z * __ldg(a1 + 4 * q + 2) + wv.w * __ldg(a1 + 4 * q + 3);
                s2 += wv.x * __ldg(a2 + 4 * q)     + wv.y * __ldg(a2 + 4 * q + 1)
                    + wv.z * __ldg(a2 + 4 * q + 2) + wv.w * __ldg(a2 + 4 * q + 3);
            }
            swa1[r * EMB + f] = s1;
            swa2[r * EMB + f] = s2;
        }
        __syncthreads();

        int slot = blockIdx.x * 256 + tid;
        int nslots = DSJB * 256;
        for (int idx = slot; idx < 4 * N_NODE; idx += nslots) {
            int n = idx >> 2;
            int rbase = (idx & 3) * 2;
            const float4* xr = (const float4*)(emb + (size_t)__ldg(x_ids + n) * EMB);
            ull xv[16];
            #pragma unroll
            for (int q = 0; q < 8; q++) {
                float4 v = __ldg(xr + q);
                xv[2 * q]     = pack2(v.x, v.y);
                xv[2 * q + 1] = pack2(v.z, v.w);
            }
            #pragma unroll
            for (int k = 0; k < 2; k++) {
                int rr = rbase + k;
                const ull* w1p = (const ull*)(swa1 + rr * EMB);
                const ull* w2p = (const ull*)(swa2 + rr * EMB);
                ull aD = 0ULL, aS = 0ULL;
                #pragma unroll
                for (int q = 0; q < 16; q++) {
                    aD = fma2(xv[q], w1p[q], aD);
                    aS = fma2(xv[q], w2p[q], aS);
                }
                g_dsj[(size_t)n * N_REL + rr] = make_float2(fold2(aD), fold2(aS));
            }
        }
    } else {
        int base = (blockIdx.x - DSJB) * 256 + tid;
        int stride = (gridDim.x - DSJB) * 256;
        for (int e = base; e < NE; e += stride) {
            int dst = ei[NE + e];
            if (!g_need[dst]) continue;
            int t = et[e];
            int pos = atomicAdd(&g_cntr8[dst * N_REL + t], 1);
            if (pos < SUBCAP)
                g_ebuf[(size_t)dst * 128 + t * SUBCAP + pos] = ei[e];
        }
    }
}

// ---------------- K3: persistent per-node aggregation, rel-sorted, routing-free ----------------
__global__ void nodeagg_k(const int* __restrict__ x_ids, const float* __restrict__ emb,
                          const float* __restrict__ root, const float* __restrict__ bias) {
    __shared__ ull   swt2[N_REL * 16 * OUT];   // 32 KB  {w[t][2q][o], w[t][2q+1][o]}
    __shared__ ull   sroot2[16 * OUT];         // 4 KB
    __shared__ int   sst[8][128];              // 4 KB  translated xsrc per slot
    __shared__ float swx[8][128];              // 4 KB  ex per slot
    __shared__ float sv[8][288];               // 9 KB  staged v (256) + x row (32)
    __shared__ float sden[8][8];

    const unsigned FULL = 0xffffffffu;
    int tid = threadIdx.x;   // 256 = 8 warps
    int wid = tid >> 5, lane = tid & 31;

    for (int i = tid; i < N_REL * 16 * OUT; i += 256) {
        int o = i & 31, q = (i >> 5) & 15, t = i >> 9;
        swt2[i] = pack2(g_w[t * 1024 + (2 * q) * 32 + o], g_w[t * 1024 + (2 * q + 1) * 32 + o]);
    }
    for (int i = tid; i < 16 * OUT; i += 256) {
        int o = i & 31, q = i >> 5;
        sroot2[i] = pack2(__ldg(root + (2 * q) * 32 + o), __ldg(root + (2 * q + 1) * 32 + o));
    }
    __syncthreads();

    float bia = __ldg(bias + lane);
    int ncnt = g_ncnt;
    int step = gridDim.x * 8;

    for (int widx = blockIdx.x * 8 + wid; widx < ncnt; widx += step) {
        int n = g_nlist[widx];
        int cnt_t = 0;
        if (lane < N_REL) {
            cnt_t = __ldg(&g_cntr8[n * N_REL + lane]);
            if (cnt_t > SUBCAP) cnt_t = SUBCAP;
        }
        float dv = (lane < N_REL) ? g_dsj[n * N_REL + lane].x : 0.f;
        const int* ebase = g_ebuf + (size_t)n * 128;

        // ---- phase 1: 4 lane-parallel rounds over 128 rel-sorted slots ----
        #pragma unroll
        for (int r = 0; r < 4; r++) {
            int slot = r * 32 + lane;
            int t = slot >> 4;          // 2r or 2r+1
            int j = slot & 15;
            int ct = __shfl_sync(FULL, cnt_t, t);
            float di = __shfl_sync(FULL, dv, t);
            bool v = (j < ct);
            float ex = 0.f;
            if (v) {
                int src = __ldg(ebase + slot);
                float sj = __ldg(&((const float*)g_dsj)[2 * (src * N_REL + t) + 1]);
                float s = di + sj;
                s = (s > 0.f) ? s : 0.2f * s;
                ex = __expf(s);
                sst[wid][slot] = __ldg(x_ids + src);
                swx[wid][slot] = ex;
            }
            // segmented butterfly within each 16-lane half (one t per half)
            float d = ex;
            d += __shfl_xor_sync(FULL, d, 1);
            d += __shfl_xor_sync(FULL, d, 2);
            d += __shfl_xor_sync(FULL, d, 4);
            d += __shfl_xor_sync(FULL, d, 8);
            if ((lane & 15) == 0) sden[wid][t] = d;
        }
        __syncwarp();
        float rd = (lane < N_REL) ? 1.f / (sden[wid][lane] + 1e-16f) : 0.f;
        unsigned tmask = __ballot_sync(FULL, (lane < N_REL) && (cnt_t > 0)) & 0xffu;

        // ---- phase 2: per-t accumulation (no routing), stage v_t ----
        #pragma unroll
        for (int t = 0; t < N_REL; t++) {
            int ct = __shfl_sync(FULL, cnt_t, t);
            float rdt = __shfl_sync(FULL, rd, t);
            if (ct == 0) continue;
            float accv = 0.f;
            for (int j0 = 0; j0 < ct; j0 += 4) {
                #pragma unroll
                for (int k = 0; k < 4; k++) {
                    int j = j0 + k;
                    int xs = sst[wid][t * SUBCAP + j];     // smem read always safe
                    float exv = swx[wid][t * SUBCAP + j];
                    float xv = (j < ct) ? __ldg(emb + (size_t)xs * EMB + lane) : 0.f;
                    accv = fmaf(xv, exv, accv);
                }
            }
            sv[wid][t * 32 + lane] = accv * rdt;
        }
        int xn = __ldg(x_ids + n);
        sv[wid][256 + lane] = __ldg(emb + (size_t)xn * EMB + lane);
        __syncwarp();

        // ---- packed transform with empty-relation skip (lane = o) ----
        ull accA = 0ULL, accB = 0ULL;
        #pragma unroll
        for (int t = 0; t < N_REL; t++) {
            if (!((tmask >> t) & 1u)) continue;
            const ull* svp = (const ull*)(sv[wid] + t * 32);
            const ull* wp = swt2 + t * 512;
            #pragma unroll
            for (int q = 0; q < 16; q += 2) {
                accA = fma2(svp[q],     wp[q * 32 + lane],       accA);
                accB = fma2(svp[q + 1], wp[(q + 1) * 32 + lane], accB);
            }
        }
        const ull* xvp = (const ull*)(sv[wid] + 256);
        #pragma unroll
        for (int q = 0; q < 16; q += 2) {
            accA = fma2(xvp[q],     sroot2[q * 32 + lane],       accA);
            accB = fma2(xvp[q + 1], sroot2[(q + 1) * 32 + lane], accB);
        }
        float acc = fold2(accA) + fold2(accB) + bia;
        g_h[n * OUT + lane] = fmaxf(acc, 0.f);
        __syncwarp();   // protect per-warp smem before next node
    }
}

// ---------------- K4: MLP, fully FFMA2-packed ----------------
__global__ void mlp_k(const int* __restrict__ users, const int* __restrict__ bundles,
                      const float* __restrict__ W1, const float* __restrict__ b1,
                      const float* __restrict__ W2, const float* __restrict__ b2,
                      const float* __restrict__ W3, const float* __restrict__ b3,
                      const float* __restrict__ Wo, const float* __restrict__ bo,
                      float* __restrict__ out) {
    __shared__ ull   sW1p[32 * H1];     // 16 KB {W1[2k][j], W1[2k+1][j]}
    __shared__ ull   sW2u[H1 * H2 / 2]; // 8 KB
    __shared__ ull   sW3u[H2 * H3 / 2]; // 2 KB
    __shared__ float sWo[H3];
    __shared__ float sb1[H1], sb2[H2], sb3[H3];

    int tid = threadIdx.x;   // 128
    for (int i = tid; i < 32 * H1; i += 128) {
        int k2 = i >> 6, j = i & 63;
        sW1p[i] = pack2(__ldg(W1 + (2 * k2) * H1 + j), __ldg(W1 + (2 * k2 + 1) * H1 + j));
    }
    {
        const float2* W2v = (const float2*)W2;
        for (int i = tid; i < H1 * H2 / 2; i += 128) {
            float2 v = __ldg(W2v + i);
            sW2u[i] = pack2(v.x, v.y);
        }
        const float2* W3v = (const float2*)W3;
        for (int i = tid; i < H2 * H3 / 2; i += 128) {
            float2 v = __ldg(W3v + i);
            sW3u[i] = pack2(v.x, v.y);
        }
    }
    if (tid < H3) sWo[tid] = Wo[tid];
    if (tid < H1) sb1[tid] = b1[tid];
    if (tid < H2) sb2[tid] = b2[tid];
    if (tid < H3) sb3[tid] = b3[tid];
    __syncthreads();

    int b = blockIdx.x * 128 + tid;
    if (b >= BATCH) return;

    int nu = users[b], nb = bundles[b];
    ull z2[32];
    const float4* hu = (const float4*)(g_h + (size_t)nu * OUT);
    const float4* hb = (const float4*)(g_h + (size_t)nb * OUT);
    #pragma unroll
    for (int k = 0; k < 8; k++) {
        float4 v = __ldg(hu + k);
        z2[2 * k]     = pack2(v.x, v.y);
        z2[2 * k + 1] = pack2(v.z, v.w);
    }
    #pragma unroll
    for (int k = 0; k < 8; k++) {
        float4 v = __ldg(hb + k);
        z2[16 + 2 * k]     = pack2(v.x, v.y);
        z2[16 + 2 * k + 1] = pack2(v.z, v.w);
    }

    ull a2p[16];
    #pragma unroll
    for (int m = 0; m < 16; m++) a2p[m] = pack2(sb2[2 * m], sb2[2 * m + 1]);
    for (int j = 0; j < H1; j++) {
        ull tA = 0ULL, tB = 0ULL;
        #pragma unroll
        for (int k2 = 0; k2 < 32; k2 += 2) {
            tA = fma2(z2[k2],     sW1p[k2 * 64 + j],       tA);
            tB = fma2(z2[k2 + 1], sW1p[(k2 + 1) * 64 + j], tB);
        }
        float t = fold2(tA) + fold2(tB) + sb1[j];
        t = fmaxf(t, 0.f);
        ull tt = pack2(t, t);
        #pragma unroll
        for (int m = 0; m < 16; m++)
            a2p[m] = fma2(tt, sW2u[j * 16 + m], a2p[m]);
    }
    float a2v[H2];
    #pragma unroll
    for (int m = 0; m < 16; m++) {
        float2 p = unpk2(a2p[m]);
        a2v[2 * m]     = fmaxf(p.x, 0.f);
        a2v[2 * m + 1] = fmaxf(p.y, 0.f);
    }

    ull a3p[8];
    #pragma unroll
    for (int m = 0; m < 8; m++) a3p[m] = pack2(sb3[2 * m], sb3[2 * m + 1]);
    #pragma unroll
    for (int j = 0; j < H2; j++) {
        ull tt = pack2(a2v[j], a2v[j]);
        #pragma unroll
        for (int m = 0; m < 8; m++)
            a3p[m] = fma2(tt, sW3u[j * 8 + m], a3p[m]);
    }
    float o = __ldg(bo);
    #pragma unroll
    for (int m = 0; m < 8; m++) {
        float2 p = unpk2(a3p[m]);
        o += fmaxf(p.x, 0.f) * sWo[2 * m] + fmaxf(p.y, 0.f) * sWo[2 * m + 1];
    }
    out[b] = o;
}

// ---------------- launch ----------------
extern "C" void kernel_launch(void* const* d_in, const int* in_sizes, int n_in,
                              void* d_out, int out_size) {
    const int*   x_ids      = (const int*)d_in[0];
    const int*   edge_index = (const int*)d_in[1];
    const int*   edge_type  = (const int*)d_in[2];
    const int*   users      = (const int*)d_in[3];
    const int*   bundles    = (const int*)d_in[4];
    const float* emb        = (const float*)d_in[5];
    const float* basis      = (const float*)d_in[6];
    const float* weight     = (const float*)d_in[7];
    const float* att        = (const float*)d_in[8];
    const float* root       = (const float*)d_in[9];
    const float* bias       = (const float*)d_in[10];
    const float* W1         = (const float*)d_in[11];
    const float* b1         = (const float*)d_in[12];
    const float* W2         = (const float*)d_in[13];
    const float* b2         = (const float*)d_in[14];
    const float* W3         = (const float*)d_in[15];
    const float* b3         = (const float*)d_in[16];
    const float* Wo         = (const float*)d_in[17];
    const float* bo         = (const float*)d_in[18];
    float* out = (float*)d_out;

    initbasis_k<<<32 + 256, 256>>>(weight, basis);                    // 0
    mark_k<<<(2 * BATCH + 255) / 256, 256>>>(users, bundles);         // 1
    prep_k<<<DSJB + 1184, 256>>>(x_ids, emb, att,
                                 edge_index, edge_type);              // 2
    nodeagg_k<<<592, 256>>>(x_ids, emb, root, bias);                  // 3  <- profiled
    mlp_k<<<BATCH / 128, 128>>>(users, bundles,
                                W1, b1, W2, b2, W3, b3, Wo, bo, out); // 4
}